// round 10
// baseline (speedup 1.0000x reference)
#include <cuda_runtime.h>

// RasterizePointsXYsBlending — single persistent kernel, latency-shortened.
// B=2, P=2048, C=64, SIZE=128, K=8, RADIUS=1.5px, RAD_POW=2, TAU=1.
//
// Grid = 148 blocks x 1024 threads (all co-resident -> grid barrier safe).
// Phase 1: blocks [0,128): transpose 2 smem tiles each (both loads in
//          flight) of src [B,C,P] -> srcT [B,P,C].
//          blocks [128,148): scatter — thread per (point, bbox-row): exact
//          inside-test, alpha via the reference's exact div/clamp/sqrt,
//          atomic append (z, alpha, idx) to 16-slot per-pixel lists.
// Grid barrier: two-counter self-resetting (invariant: both counters 0).
// Phase 2: blocks [0,128): composite. Block = 8 pixel-groups x 4 cg-warps.
//          cg0 warp reads+clears d_cnt, publishes via smem (+syncthreads =
//          block-wide read-before-clear). All warps speculatively load list
//          entries 0,1 in parallel with the count. cnt==1/2 fast paths;
//          order-independent O(n^2) weights for 3..8; top-8 fallback >8.

#define BN 2
#define PN 2048
#define CN 64
#define SZ 128
#define KN 8
#define BIGF 1e10f
// r_ndc = 1.5/128*2 = 3*2^-7 ; r2 = 9*2^-14 (exact fp32)
#define R2 0.00054931640625f

#define CAPP 16
#define NPIX (BN * SZ * SZ)           // 32768
#define NBLK 148
#define NTHR 1024
#define CMPB 128                      // composite / transpose blocks
#define NSCAT (BN * PN * 4)           // 16384 scatter items

__device__ float  d_srcT[BN * PN * CN];   // src transposed to [b,p,c]
__device__ int    d_cnt[NPIX];            // per-pixel counts (invariant: 0)
__device__ float4 d_list[NPIX * CAPP];    // (z, alpha, bitcast idx, -)
__device__ int    d_bin;                  // barrier arrivals (invariant: 0)
__device__ int    d_bout;                 // barrier exits    (invariant: 0)

__global__ __launch_bounds__(NTHR, 1)
void fused_kernel(const float* __restrict__ pts,
                  const float* __restrict__ src,
                  float* __restrict__ out)
{
    __shared__ float tile[2][32][33];
    __shared__ int   s_cnt[8][32];

    const int tid = threadIdx.x;
    const int bid = blockIdx.x;

    // ================= phase 1 =================
    if (bid < CMPB) {
        // transpose: 2 tiles per block, both loads in flight.
        const int x = tid & 31;
        const int y = tid >> 5;
#pragma unroll
        for (int q = 0; q < 2; ++q) {
            const int t  = bid + q * CMPB;       // exactly covers 256 tiles
            const int b  = t >> 7;
            const int c0 = ((t >> 6) & 1) * 32;
            const int p0 = (t & 63) * 32;
            tile[q][y][x] = src[((size_t)(b * CN + c0 + y) << 11) + p0 + x];
        }
        __syncthreads();
#pragma unroll
        for (int q = 0; q < 2; ++q) {
            const int t  = bid + q * CMPB;
            const int b  = t >> 7;
            const int c0 = ((t >> 6) & 1) * 32;
            const int p0 = (t & 63) * 32;
            d_srcT[((size_t)(b * PN + p0 + y) << 6) + c0 + x] = tile[q][x][y];
        }
    } else {
        // scatter: thread per (point, bbox-row)
        const int s = (bid - CMPB) * NTHR + tid;
        if (s < NSCAT) {
            const int ry = s & 3;
            const int gp = s >> 2;
            const int b  = gp >> 11;
            const int p  = gp & (PN - 1);

            const float px = -pts[gp * 3 + 0];   // sign flip from forward
            const float py = -pts[gp * 3 + 1];
            const float pz =  pts[gp * 3 + 2];

            const float u = (1.0f - px) * 64.0f - 0.5f;
            const float v = (1.0f - py) * 64.0f - 0.5f;

            const int wlo = max(0,      (int)ceilf (u - 1.6f));
            const int whi = min(SZ - 1, (int)floorf(u + 1.6f));
            const int hlo = max(0,      (int)ceilf (v - 1.6f));
            const int hhi = min(SZ - 1, (int)floorf(v + 1.6f));

            const int h = hlo + ry;
            if (h <= hhi && wlo <= whi) {
                const float ndcy = 1.0f - (2.0f * (float)h + 1.0f) / 128.0f;
                const float dy   = ndcy - py;
                const float dy2  = __fmul_rn(dy, dy);

                for (int w = wlo; w <= whi; ++w) {
                    const float ndcx = 1.0f - (2.0f * (float)w + 1.0f) / 128.0f;
                    const float dx   = ndcx - px;
                    // non-fused: matches reference rounding at the boundary
                    const float d2 = __fadd_rn(__fmul_rn(dx, dx), dy2);
                    if (d2 <= R2) {
                        float dist = __fdiv_rn(d2, R2);
                        dist = fminf(fmaxf(dist, 0.001f), 1.0f);
                        const float a = 1.0f - __fsqrt_rn(dist);

                        const int pix  = ((b * SZ) + h) * SZ + w;
                        const int slot = atomicAdd(&d_cnt[pix], 1);
                        if (slot < CAPP)
                            d_list[pix * CAPP + slot] =
                                make_float4(pz, a, __int_as_float(p), 0.0f);
                    }
                }
            }
        }
    }

    // ================= grid barrier (self-resetting) =================
    __syncthreads();
    if (tid == 0) {
        __threadfence();
        atomicAdd(&d_bin, 1);
        while (*(volatile int*)&d_bin < NBLK) __nanosleep(32);
        __threadfence();
    }
    __syncthreads();

    // ================= phase 2: composite =================
    if (bid < CMPB) {
        const int lane = tid & 31;
        const int wy   = tid >> 5;            // 0..31
        const int pg   = wy & 7;              // pixel group within block
        const int cg   = wy >> 3;             // channel group 0..3
        const int pix  = (bid * 8 + pg) * 32 + lane;

        const int w = pix & (SZ - 1);
        const int h = (pix >> 7) & (SZ - 1);
        const int b = pix >> 14;

        // cg0 warp reads + clears the counter; smem + barrier publishes it
        // (block-wide read-before-clear, no cross-warp race).
        if (cg == 0) {
            const int c = d_cnt[pix];
            s_cnt[pg][lane] = c;
            d_cnt[pix] = 0;                   // restore all-zero invariant
        }
        // speculative list loads — independent of the counter
        const float4* lp = d_list + pix * CAPP;
        const float4 e0 = lp[0];
        const float4 e1 = lp[1];
        __syncthreads();
        const int cnt = min(s_cnt[pg][lane], CAPP);

        float acc[16];
#pragma unroll
        for (int j = 0; j < 16; ++j) acc[j] = 0.0f;

        const float* sbase = d_srcT + (((size_t)b * PN) << 6) + cg * 16;
        auto gather = [&](int idx, float wi) {
            const float4* s4 = (const float4*)(sbase + ((size_t)idx << 6));
#pragma unroll
            for (int q = 0; q < 4; ++q) {
                const float4 v = s4[q];
                acc[4 * q + 0] = fmaf(wi, v.x, acc[4 * q + 0]);
                acc[4 * q + 1] = fmaf(wi, v.y, acc[4 * q + 1]);
                acc[4 * q + 2] = fmaf(wi, v.z, acc[4 * q + 2]);
                acc[4 * q + 3] = fmaf(wi, v.w, acc[4 * q + 3]);
            }
        };

        if (cnt == 1) {
            if (e0.y > 0.0f) gather(__float_as_int(e0.z), e0.y);
        } else if (cnt == 2) {
            const float w0 = (e1.x < e0.x) ? e0.y * (1.0f - e1.y) : e0.y;
            const float w1 = (e0.x < e1.x) ? e1.y * (1.0f - e0.y) : e1.y;
            if (w0 > 0.0f) gather(__float_as_int(e0.z), w0);
            if (w1 > 0.0f) gather(__float_as_int(e1.z), w1);
        } else if (cnt > 2) {
            if (cnt <= KN) {
                // order-independent weights: w_i = a_i*prod_{z_j<z_i}(1-a_j)
                for (int i = 0; i < cnt; ++i) {
                    const float4 ei = lp[i];
                    float wi = ei.y;
                    for (int j = 0; j < cnt; ++j) {
                        if (j == i) continue;
                        const float4 ej = lp[j];
                        if (ej.x < ei.x) wi *= (1.0f - ej.y);
                    }
                    if (wi > 0.0f) gather(__float_as_int(ei.z), wi);
                }
            } else {
                // cold: top-8 by z (insertion), sequential cumprod
                float zb[KN], ab[KN];
                int   ib[KN];
#pragma unroll
                for (int k = 0; k < KN; ++k) { zb[k] = BIGF; ab[k] = 0.0f; ib[k] = 0; }
                for (int i = 0; i < cnt; ++i) {
                    const float4 e = lp[i];
                    if (e.x < zb[KN - 1]) {
                        float cz = e.x, ca = e.y;
                        int   ci = __float_as_int(e.z);
                        bool  ins = false;
#pragma unroll
                        for (int k = 0; k < KN; ++k) {
                            bool sw = ins | (cz < zb[k]);
                            if (sw) {
                                float tz = zb[k]; zb[k] = cz; cz = tz;
                                float ta = ab[k]; ab[k] = ca; ca = ta;
                                int   ti = ib[k]; ib[k] = ci; ci = ti;
                                ins = true;
                            }
                        }
                    }
                }
                float T = 1.0f;
#pragma unroll
                for (int k = 0; k < KN; ++k) {
                    if (zb[k] < BIGF) {
                        const float wi = ab[k] * T;
                        T = T * (1.0f - ab[k]);
                        if (wi > 0.0f) gather(ib[k], wi);
                    }
                }
            }
        }

        // out[b,c,h,w]; lane = w -> coalesced 128B stores per plane
        float* ob = out + (((size_t)(b * CN + cg * 16)) * SZ + h) * SZ + w;
#pragma unroll
        for (int j = 0; j < 16; ++j)
            ob[(size_t)j * SZ * SZ] = acc[j];
    }

    // ================= barrier counter reset =================
    __syncthreads();
    if (tid == 0) {
        const int old = atomicAdd(&d_bout, 1);
        if (old == NBLK - 1) {
            *(volatile int*)&d_bin  = 0;
            *(volatile int*)&d_bout = 0;
        }
    }
}

// ---------------------------------------------------------------- launch
extern "C" void kernel_launch(void* const* d_in, const int* in_sizes, int n_in,
                              void* d_out, int out_size)
{
    const float* pts = (const float*)d_in[0];  // [B,P,3]
    const float* src = (const float*)d_in[1];  // [B,C,P]
    float* out = (float*)d_out;                // [B,C,H,W]

    fused_kernel<<<NBLK, NTHR>>>(pts, src, out);
}

// round 11
// speedup vs baseline: 1.1199x; 1.1199x over previous
#include <cuda_runtime.h>

// RasterizePointsXYsBlending — 2 kernels, MLP-optimized prep + spec-load composite.
// B=2, P=2048, C=64, SIZE=128, K=8, RADIUS=1.5px, RAD_POW=2, TAU=1.
//
//  K1 prep (192 blocks x 256 thr):
//     blocks [0,128):  transpose src [B,C,P] -> srcT [B,P,C]. Each block
//                      does 2 32x32 tiles; per thread 2 independent LDG.128
//                      issued back-to-back (MLP=8 sectors) before the sync.
//     blocks [128,192): scatter — thread per (point, bbox-row): exact
//                      inside-test on <=4 pixels, alpha via the reference's
//                      exact div/clamp/sqrt, atomic append (z, alpha, idx).
//  K2 composite (1024 blocks x (32,4)) — R8 structure: 4 warps/pixel-row,
//     16 channels/thread, warp = 32 consecutive w (coalesced stores).
//     Counter: all read, __syncthreads, cg0 clears (read-before-clear).
//     NEW: list entries 0,1 loaded speculatively in parallel with the
//     counter (fixed addresses); cnt==1/2 closed-form fast paths.

#define BN 2
#define PN 2048
#define CN 64
#define SZ 128
#define KN 8
#define BIGF 1e10f
// r_ndc = 1.5/128*2 = 3*2^-7 ; r2 = 9*2^-14 (exact fp32)
#define R2 0.00054931640625f

#define CAPP 16                       // per-pixel list capacity (mean ~0.9)
#define NPIX (BN * SZ * SZ)           // 32768
#define TRB 128                       // transpose blocks (2 tiles each)
#define SCB 64                        // scatter blocks (64*256 = BN*PN*4)
#define NSCAT (BN * PN * 4)

__device__ float  d_srcT[BN * PN * CN];   // src transposed to [b,p,c]
__device__ int    d_cnt[NPIX];            // per-pixel counts (invariant: 0)
__device__ float4 d_list[NPIX * CAPP];    // (z, alpha, bitcast idx, -)

// ---------------------------------------------------------------- kernel 1
__global__ __launch_bounds__(256)
void prep_kernel(const float* __restrict__ src, const float* __restrict__ pts)
{
    if (blockIdx.x < TRB) {
        // -------- transpose: 2 tiles/block, 2 independent LDG.128/thread --
        __shared__ float t[2][32][33];
        const int i  = threadIdx.x;
        const int y  = i >> 3;            // 0..31 (channel row in tile)
        const int xq = (i & 7) * 4;       // 0,4,...,28 (p quad)

        float4 v[2];
#pragma unroll
        for (int q = 0; q < 2; ++q) {
            const int tl = blockIdx.x + q * TRB;     // covers 256 tiles
            const int b  = tl >> 7;
            const int c0 = ((tl >> 6) & 1) * 32;
            const int p0 = (tl & 63) * 32;
            v[q] = *(const float4*)
                (src + ((size_t)(b * CN + c0 + y) << 11) + p0 + xq);
        }
#pragma unroll
        for (int q = 0; q < 2; ++q) {
            t[q][y][xq + 0] = v[q].x;
            t[q][y][xq + 1] = v[q].y;
            t[q][y][xq + 2] = v[q].z;
            t[q][y][xq + 3] = v[q].w;
        }
        __syncthreads();

        const int c  = i & 31;            // output lane = channel
        const int pq = i >> 5;            // 0..7 (p row group of 4)
#pragma unroll
        for (int q = 0; q < 2; ++q) {
            const int tl = blockIdx.x + q * TRB;
            const int b  = tl >> 7;
            const int c0 = ((tl >> 6) & 1) * 32;
            const int p0 = (tl & 63) * 32;
#pragma unroll
            for (int r = 0; r < 4; ++r) {
                const int p = pq * 4 + r;
                d_srcT[((size_t)(b * PN + p0 + p) << 6) + c0 + c] =
                    t[q][c][p];
            }
        }
    } else {
        // ---------------- scatter: (point, bbox-row) ---------------------
        const int s = (blockIdx.x - TRB) * 256 + threadIdx.x;
        if (s < NSCAT) {
            const int ry = s & 3;
            const int gp = s >> 2;
            const int b  = gp >> 11;
            const int p  = gp & (PN - 1);

            const float px = -pts[gp * 3 + 0];   // sign flip from forward
            const float py = -pts[gp * 3 + 1];
            const float pz =  pts[gp * 3 + 2];

            const float u = (1.0f - px) * 64.0f - 0.5f;
            const float v = (1.0f - py) * 64.0f - 0.5f;

            const int wlo = max(0,      (int)ceilf (u - 1.6f));
            const int whi = min(SZ - 1, (int)floorf(u + 1.6f));
            const int hlo = max(0,      (int)ceilf (v - 1.6f));
            const int hhi = min(SZ - 1, (int)floorf(v + 1.6f));

            const int h = hlo + ry;
            if (h <= hhi && wlo <= whi) {
                const float ndcy = 1.0f - (2.0f * (float)h + 1.0f) / 128.0f;
                const float dy   = ndcy - py;
                const float dy2  = __fmul_rn(dy, dy);

                for (int w = wlo; w <= whi; ++w) {
                    const float ndcx = 1.0f - (2.0f * (float)w + 1.0f) / 128.0f;
                    const float dx   = ndcx - px;
                    // non-fused: matches reference rounding at the boundary
                    const float d2 = __fadd_rn(__fmul_rn(dx, dx), dy2);
                    if (d2 <= R2) {
                        float dist = __fdiv_rn(d2, R2);
                        dist = fminf(fmaxf(dist, 0.001f), 1.0f);
                        const float a = 1.0f - __fsqrt_rn(dist);

                        const int pix  = ((b * SZ) + h) * SZ + w;
                        const int slot = atomicAdd(&d_cnt[pix], 1);
                        if (slot < CAPP)
                            d_list[pix * CAPP + slot] =
                                make_float4(pz, a, __int_as_float(p), 0.0f);
                    }
                }
            }
        }
    }
}

// ---------------------------------------------------------------- kernel 2
// Block (32,4): 32 pixels (lane = w) x 4 channel-groups (16 ch/thread).
// grid = BN*SZ*(SZ/32) = 1024 blocks.
__global__ __launch_bounds__(128)
void composite_kernel(float* __restrict__ out)
{
    const int wt = blockIdx.x & 3;
    const int h  = (blockIdx.x >> 2) & (SZ - 1);
    const int b  = blockIdx.x >> 9;
    const int x  = threadIdx.x;
    const int w  = wt * 32 + x;
    const int cg = threadIdx.y;              // channel group: 16 channels
    const int pix = ((b * SZ) + h) * SZ + w;

    // counter + speculative list head, all in one parallel L2 round trip
    const int cnt_raw = d_cnt[pix];
    const float4* lp = d_list + pix * CAPP;
    const float4 e0 = lp[0];
    const float4 e1 = lp[1];

    // read-before-clear (block-wide)
    __syncthreads();
    if (cg == 0) d_cnt[pix] = 0;             // restore all-zero invariant
    const int cnt = min(cnt_raw, CAPP);

    float acc[16];
#pragma unroll
    for (int j = 0; j < 16; ++j) acc[j] = 0.0f;

    const float* sbase = d_srcT + (((size_t)b * PN) << 6) + cg * 16;
    auto gather = [&](int idx, float wi) {
        const float4* s4 = (const float4*)(sbase + ((size_t)idx << 6));
#pragma unroll
        for (int q = 0; q < 4; ++q) {
            const float4 v = s4[q];
            acc[4 * q + 0] = fmaf(wi, v.x, acc[4 * q + 0]);
            acc[4 * q + 1] = fmaf(wi, v.y, acc[4 * q + 1]);
            acc[4 * q + 2] = fmaf(wi, v.z, acc[4 * q + 2]);
            acc[4 * q + 3] = fmaf(wi, v.w, acc[4 * q + 3]);
        }
    };

    if (cnt == 1) {
        if (e0.y > 0.0f) gather(__float_as_int(e0.z), e0.y);
    } else if (cnt == 2) {
        const float w0 = (e1.x < e0.x) ? e0.y * (1.0f - e1.y) : e0.y;
        const float w1 = (e0.x < e1.x) ? e1.y * (1.0f - e0.y) : e1.y;
        if (w0 > 0.0f) gather(__float_as_int(e0.z), w0);
        if (w1 > 0.0f) gather(__float_as_int(e1.z), w1);
    } else if (cnt > 2) {
        if (cnt <= KN) {
            // order-independent weights: w_i = a_i * prod_{z_j<z_i}(1-a_j)
            for (int i = 0; i < cnt; ++i) {
                const float4 ei = lp[i];
                float wi = ei.y;
                for (int j = 0; j < cnt; ++j) {
                    if (j == i) continue;
                    const float4 ej = lp[j];
                    if (ej.x < ei.x) wi *= (1.0f - ej.y);
                }
                if (wi > 0.0f) gather(__float_as_int(ei.z), wi);
            }
        } else {
            // cold path: top-8 by z (insertion), sequential cumprod
            float zb[KN], ab[KN];
            int   ib[KN];
#pragma unroll
            for (int k = 0; k < KN; ++k) { zb[k] = BIGF; ab[k] = 0.0f; ib[k] = 0; }
            for (int i = 0; i < cnt; ++i) {
                const float4 e = lp[i];
                if (e.x < zb[KN - 1]) {
                    float cz = e.x, ca = e.y;
                    int   ci = __float_as_int(e.z);
                    bool  ins = false;
#pragma unroll
                    for (int k = 0; k < KN; ++k) {
                        bool sw = ins | (cz < zb[k]);
                        if (sw) {
                            float tz = zb[k]; zb[k] = cz; cz = tz;
                            float ta = ab[k]; ab[k] = ca; ca = ta;
                            int   ti = ib[k]; ib[k] = ci; ci = ti;
                            ins = true;
                        }
                    }
                }
            }
            float T = 1.0f;
#pragma unroll
            for (int k = 0; k < KN; ++k) {
                if (zb[k] < BIGF) {
                    const float wi = ab[k] * T;
                    T = T * (1.0f - ab[k]);
                    if (wi > 0.0f) gather(ib[k], wi);
                }
            }
        }
    }

    // out[b,c,h,w]; lane = w -> coalesced 128B stores per channel plane
    float* ob = out + (((size_t)(b * CN + cg * 16)) * SZ + h) * SZ + w;
#pragma unroll
    for (int j = 0; j < 16; ++j)
        ob[(size_t)j * SZ * SZ] = acc[j];
}

// ---------------------------------------------------------------- launch
extern "C" void kernel_launch(void* const* d_in, const int* in_sizes, int n_in,
                              void* d_out, int out_size)
{
    const float* pts = (const float*)d_in[0];  // [B,P,3]
    const float* src = (const float*)d_in[1];  // [B,C,P]
    float* out = (float*)d_out;                // [B,C,H,W]

    prep_kernel<<<TRB + SCB, 256>>>(src, pts);
    composite_kernel<<<BN * SZ * (SZ / 32), dim3(32, 4)>>>(out);
}

// round 12
// speedup vs baseline: 1.4693x; 1.3120x over previous
#include <cuda_runtime.h>

// RasterizePointsXYsBlending — flat scatter + R8 composite.
// B=2, P=2048, C=64, SIZE=128, K=8, RADIUS=1.5px, RAD_POW=2, TAU=1.
//
//  K1 prep (384 blocks x 256 thr):
//     blocks [0,128):  transpose src [B,C,P] -> srcT [B,P,C]; 2 tiles per
//                      block, 2 independent LDG.128 per thread (MLP=8).
//     blocks [128,384): scatter — ONE THREAD PER (point, 4x4 bbox cell):
//                      <=1 exact inside-test, <=1 atomic append — the
//                      dependent atomic->store chain has depth 1.
//  K2 composite (1024 blocks x (32,4)) — R8 structure verbatim:
//     warp = 32 consecutive w (coalesced stores), 16 channels/thread;
//     counter: all read, __syncthreads, cg0 clears (read-before-clear);
//     cnt<=8: order-independent weights w_i = a_i*prod_{z_j<z_i}(1-a_j);
//     cold top-8 insertion fallback for cnt>8.

#define BN 2
#define PN 2048
#define CN 64
#define SZ 128
#define KN 8
#define BIGF 1e10f
// r_ndc = 1.5/128*2 = 3*2^-7 ; r2 = 9*2^-14 (exact fp32)
#define R2 0.00054931640625f

#define CAPP 16                       // per-pixel list capacity (mean ~0.9)
#define NPIX (BN * SZ * SZ)           // 32768
#define TRB 128                       // transpose blocks (2 tiles each)
#define SCB 256                       // scatter blocks (256*256 = BN*PN*16)
#define NSCAT (BN * PN * 16)          // one item per (point, bbox cell)

__device__ float  d_srcT[BN * PN * CN];   // src transposed to [b,p,c]
__device__ int    d_cnt[NPIX];            // per-pixel counts (invariant: 0)
__device__ float4 d_list[NPIX * CAPP];    // (z, alpha, bitcast idx, -)

// ---------------------------------------------------------------- kernel 1
__global__ __launch_bounds__(256)
void prep_kernel(const float* __restrict__ src, const float* __restrict__ pts)
{
    if (blockIdx.x < TRB) {
        // -------- transpose: 2 tiles/block, 2 independent LDG.128/thread --
        __shared__ float t[2][32][33];
        const int i  = threadIdx.x;
        const int y  = i >> 3;            // 0..31 (channel row in tile)
        const int xq = (i & 7) * 4;       // 0,4,...,28 (p quad)

        float4 v[2];
#pragma unroll
        for (int q = 0; q < 2; ++q) {
            const int tl = blockIdx.x + q * TRB;     // covers 256 tiles
            const int b  = tl >> 7;
            const int c0 = ((tl >> 6) & 1) * 32;
            const int p0 = (tl & 63) * 32;
            v[q] = *(const float4*)
                (src + ((size_t)(b * CN + c0 + y) << 11) + p0 + xq);
        }
#pragma unroll
        for (int q = 0; q < 2; ++q) {
            t[q][y][xq + 0] = v[q].x;
            t[q][y][xq + 1] = v[q].y;
            t[q][y][xq + 2] = v[q].z;
            t[q][y][xq + 3] = v[q].w;
        }
        __syncthreads();

        const int c  = i & 31;            // output lane = channel
        const int pq = i >> 5;            // 0..7 (p row group of 4)
#pragma unroll
        for (int q = 0; q < 2; ++q) {
            const int tl = blockIdx.x + q * TRB;
            const int b  = tl >> 7;
            const int c0 = ((tl >> 6) & 1) * 32;
            const int p0 = (tl & 63) * 32;
#pragma unroll
            for (int r = 0; r < 4; ++r) {
                const int p = pq * 4 + r;
                d_srcT[((size_t)(b * PN + p0 + p) << 6) + c0 + c] =
                    t[q][c][p];
            }
        }
    } else {
        // ------- scatter: one thread per (point, 4x4 bbox cell) ----------
        const int s = (blockIdx.x - TRB) * 256 + threadIdx.x;
        const int cell = s & 15;
        const int rx   = cell & 3;
        const int ry   = cell >> 2;
        const int gp   = s >> 4;               // global point id
        const int b    = gp >> 11;
        const int p    = gp & (PN - 1);

        const float px = -pts[gp * 3 + 0];     // sign flip from forward
        const float py = -pts[gp * 3 + 1];
        const float pz =  pts[gp * 3 + 2];

        // pixel coords of the point: ndc(i) = 1-(2i+1)/128
        const float u = (1.0f - px) * 64.0f - 0.5f;   // w
        const float v = (1.0f - py) * 64.0f - 0.5f;   // h

        // radius 1.5 px + fp margin; bbox spans <=4 cells per axis
        const int wlo = max(0,      (int)ceilf (u - 1.6f));
        const int whi = min(SZ - 1, (int)floorf(u + 1.6f));
        const int hlo = max(0,      (int)ceilf (v - 1.6f));
        const int hhi = min(SZ - 1, (int)floorf(v + 1.6f));

        const int w = wlo + rx;
        const int h = hlo + ry;
        if (w <= whi && h <= hhi) {
            const float ndcy = 1.0f - (2.0f * (float)h + 1.0f) / 128.0f;
            const float ndcx = 1.0f - (2.0f * (float)w + 1.0f) / 128.0f;
            const float dx = ndcx - px;
            const float dy = ndcy - py;
            // mul/mul/add, non-fused: matches reference rounding exactly
            const float d2 =
                __fadd_rn(__fmul_rn(dx, dx), __fmul_rn(dy, dy));
            if (d2 <= R2) {
                // alpha with the reference's exact op sequence
                float dist = __fdiv_rn(d2, R2);
                dist = fminf(fmaxf(dist, 0.001f), 1.0f);
                const float a = 1.0f - __fsqrt_rn(dist);

                const int pix  = ((b * SZ) + h) * SZ + w;
                const int slot = atomicAdd(&d_cnt[pix], 1);
                if (slot < CAPP)
                    d_list[pix * CAPP + slot] =
                        make_float4(pz, a, __int_as_float(p), 0.0f);
            }
        }
    }
}

// ---------------------------------------------------------------- kernel 2
// Block (32,4): 32 pixels (lane = w) x 4 channel-groups (16 ch/thread).
// grid = BN*SZ*(SZ/32) = 1024 blocks.  (R8 structure.)
__global__ __launch_bounds__(128)
void composite_kernel(float* __restrict__ out)
{
    const int wt = blockIdx.x & 3;
    const int h  = (blockIdx.x >> 2) & (SZ - 1);
    const int b  = blockIdx.x >> 9;
    const int x  = threadIdx.x;
    const int w  = wt * 32 + x;
    const int cg = threadIdx.y;              // channel group: 16 channels
    const int pix = ((b * SZ) + h) * SZ + w;

    // read-before-clear: every warp loads the counter, barrier, then clear.
    const int cnt = min(d_cnt[pix], CAPP);
    __syncthreads();
    if (cg == 0) d_cnt[pix] = 0;             // restore all-zero invariant

    float acc[16];
#pragma unroll
    for (int j = 0; j < 16; ++j) acc[j] = 0.0f;

    const float4* lp = d_list + pix * CAPP;
    const float*  sbase = d_srcT + (((size_t)b * PN) << 6) + cg * 16;

    if (cnt <= KN) {
        // ---- common path: all points selected; order-independent weights
        for (int i = 0; i < cnt; ++i) {
            const float4 ei = lp[i];
            float wi = ei.y;                              // a_i
            for (int j = 0; j < cnt; ++j) {
                if (j == i) continue;
                const float4 ej = lp[j];
                if (ej.x < ei.x) wi *= (1.0f - ej.y);
            }
            if (wi > 0.0f) {
                const float4* s4 = (const float4*)
                    (sbase + ((size_t)__float_as_int(ei.z) << 6));
#pragma unroll
                for (int q = 0; q < 4; ++q) {
                    const float4 v = s4[q];
                    acc[4 * q + 0] = fmaf(wi, v.x, acc[4 * q + 0]);
                    acc[4 * q + 1] = fmaf(wi, v.y, acc[4 * q + 1]);
                    acc[4 * q + 2] = fmaf(wi, v.z, acc[4 * q + 2]);
                    acc[4 * q + 3] = fmaf(wi, v.w, acc[4 * q + 3]);
                }
            }
        }
    } else {
        // ---- cold path: top-8 by z (insertion), then sequential cumprod
        float zb[KN], ab[KN];
        int   ib[KN];
#pragma unroll
        for (int k = 0; k < KN; ++k) { zb[k] = BIGF; ab[k] = 0.0f; ib[k] = 0; }
        for (int i = 0; i < cnt; ++i) {
            const float4 e = lp[i];
            if (e.x < zb[KN - 1]) {
                float cz = e.x, ca = e.y;
                int   ci = __float_as_int(e.z);
                bool  ins = false;
#pragma unroll
                for (int k = 0; k < KN; ++k) {
                    bool sw = ins | (cz < zb[k]);
                    if (sw) {
                        float tz = zb[k]; zb[k] = cz; cz = tz;
                        float ta = ab[k]; ab[k] = ca; ca = ta;
                        int   ti = ib[k]; ib[k] = ci; ci = ti;
                        ins = true;
                    }
                }
            }
        }
        float T = 1.0f;
#pragma unroll
        for (int k = 0; k < KN; ++k) {
            if (zb[k] < BIGF) {
                const float wi = ab[k] * T;
                T = T * (1.0f - ab[k]);
                if (wi > 0.0f) {
                    const float4* s4 = (const float4*)
                        (sbase + ((size_t)ib[k] << 6));
#pragma unroll
                    for (int q = 0; q < 4; ++q) {
                        const float4 v = s4[q];
                        acc[4 * q + 0] = fmaf(wi, v.x, acc[4 * q + 0]);
                        acc[4 * q + 1] = fmaf(wi, v.y, acc[4 * q + 1]);
                        acc[4 * q + 2] = fmaf(wi, v.z, acc[4 * q + 2]);
                        acc[4 * q + 3] = fmaf(wi, v.w, acc[4 * q + 3]);
                    }
                }
            }
        }
    }

    // out[b,c,h,w]; lane = w -> coalesced 128B stores per channel plane
    float* ob = out + (((size_t)(b * CN + cg * 16)) * SZ + h) * SZ + w;
#pragma unroll
    for (int j = 0; j < 16; ++j)
        ob[(size_t)j * SZ * SZ] = acc[j];
}

// ---------------------------------------------------------------- launch
extern "C" void kernel_launch(void* const* d_in, const int* in_sizes, int n_in,
                              void* d_out, int out_size)
{
    const float* pts = (const float*)d_in[0];  // [B,P,3]
    const float* src = (const float*)d_in[1];  // [B,C,P]
    float* out = (float*)d_out;                // [B,C,H,W]

    prep_kernel<<<TRB + SCB, 256>>>(src, pts);
    composite_kernel<<<BN * SZ * (SZ / 32), dim3(32, 4)>>>(out);
}